// round 7
// baseline (speedup 1.0000x reference)
#include <cuda_runtime.h>
#include <cuda_bf16.h>
#include <cstdint>
#include <cmath>

// Problem: B=64, T=512, E=256, U=256, bidirectional LSTM (all-tanh), mask carry.

// ---------------------------------------------------------------------------
// Device scratch
// ---------------------------------------------------------------------------
__device__ float g_Z[2ull * 512 * 64 * 1024];                  // [dir][t][b][u*4+g]
__device__ unsigned char g_mask[64 * 512];                     // [b][t]
__device__ __align__(16) __nv_bfloat16 g_Xhi[32768ull * 256];  // [m=t*64+b][k]
__device__ __align__(16) __nv_bfloat16 g_Xlo[32768ull * 256];
__device__ __align__(16) __nv_bfloat16 g_Whi[2ull * 1024 * 256]; // [dir][q=u*4+g][k]
__device__ __align__(16) __nv_bfloat16 g_Wlo[2ull * 1024 * 256];

// ---------------------------------------------------------------------------
// PTX helpers (family-level features only)
// ---------------------------------------------------------------------------
__device__ __forceinline__ uint32_t smem_u32(const void* p)
{
    uint32_t a;
    asm("{ .reg .u64 t; cvta.to.shared.u64 t, %1; cvt.u32.u64 %0, t; }"
        : "=r"(a) : "l"(p));
    return a;
}

#define CP_ASYNC16(dst, src) \
    asm volatile("cp.async.cg.shared.global [%0], [%1], 16;" \
                 :: "r"(dst), "l"(src) : "memory")
#define CP_ASYNC_COMMIT() asm volatile("cp.async.commit_group;" ::: "memory")
#define CP_ASYNC_WAIT(n)  asm volatile("cp.async.wait_group %0;" :: "n"(n) : "memory")

__device__ __forceinline__ void ldm4(uint32_t* r, uint32_t addr)
{
    asm volatile("ldmatrix.sync.aligned.m8n8.x4.shared.b16 {%0,%1,%2,%3}, [%4];"
                 : "=r"(r[0]), "=r"(r[1]), "=r"(r[2]), "=r"(r[3]) : "r"(addr));
}

__device__ __forceinline__ void mma16816(float* c, const uint32_t* a,
                                         uint32_t b0, uint32_t b1)
{
    asm volatile(
        "mma.sync.aligned.m16n8k16.row.col.f32.bf16.bf16.f32 "
        "{%0,%1,%2,%3}, {%4,%5,%6,%7}, {%8,%9}, {%0,%1,%2,%3};"
        : "+f"(c[0]), "+f"(c[1]), "+f"(c[2]), "+f"(c[3])
        : "r"(a[0]), "r"(a[1]), "r"(a[2]), "r"(a[3]), "r"(b0), "r"(b1));
}

__device__ __forceinline__ uint32_t mapa_rank(uint32_t addr, uint32_t rank)
{
    uint32_t r;
    asm("mapa.shared::cluster.u32 %0, %1, %2;" : "=r"(r) : "r"(addr), "r"(rank));
    return r;
}
#define ST_CLUSTER_U32(addr, v) \
    asm volatile("st.shared::cluster.u32 [%0], %1;" :: "r"(addr), "r"(v) : "memory")

#define MBARRIER_INIT(addr, count) \
    asm volatile("mbarrier.init.shared.b64 [%0], %1;" \
                 :: "r"((uint32_t)(addr)), "r"((uint32_t)(count)) : "memory")
#define MBAR_ARRIVE_REL_CLUSTER(addr) \
    asm volatile("mbarrier.arrive.release.cluster.shared::cluster.b64 _, [%0];" \
                 :: "r"((uint32_t)(addr)) : "memory")

#define MBAR_WAIT_ACQ_CLUSTER(mbar, parity) do { \
    uint32_t _m = (uint32_t)(mbar); \
    uint32_t _p = (uint32_t)(parity); \
    uint32_t _done; \
    asm volatile( \
        "{\n\t.reg .pred p;\n\t" \
        "mbarrier.try_wait.parity.acquire.cluster.shared::cta.b64 p, [%1], %2;\n\t" \
        "selp.b32 %0, 1, 0, p;\n\t}" \
        : "=r"(_done) : "r"(_m), "r"(_p) : "memory"); \
    if (!_done) { \
        asm volatile( \
            "{\n\t.reg .pred P1;\n\t" \
            "WL_%=:\n\t" \
            "mbarrier.try_wait.parity.acquire.cluster.shared::cta.b64 P1, [%0], %1, 0x989680;\n\t" \
            "@P1 bra.uni WD_%=;\n\t" \
            "bra.uni WL_%=;\n\t" \
            "WD_%=:\n\t}" \
            :: "r"(_m), "r"(_p) : "memory"); \
    } \
} while (0)

#define CLUSTER_SYNC() do { \
    asm volatile("barrier.cluster.arrive.aligned;" ::: "memory"); \
    asm volatile("barrier.cluster.wait.aligned;"   ::: "memory"); \
} while (0)

// ---------------------------------------------------------------------------
// Mask kernel: mask[b][t] = any(x[b,t,:] != 0)
// ---------------------------------------------------------------------------
__global__ void mask_kernel(const float* __restrict__ x)
{
    int gw   = (blockIdx.x * blockDim.x + threadIdx.x) >> 5;
    int lane = threadIdx.x & 31;
    if (gw >= 64 * 512) return;
    const float4* p = reinterpret_cast<const float4*>(x + (size_t)gw * 256);
    float4 a = p[lane];
    float4 b = p[lane + 32];
    bool nz = (a.x != 0.f) || (a.y != 0.f) || (a.z != 0.f) || (a.w != 0.f) ||
              (b.x != 0.f) || (b.y != 0.f) || (b.z != 0.f) || (b.w != 0.f);
    unsigned m = __ballot_sync(0xffffffffu, nz);
    if (lane == 0) g_mask[gw] = (m != 0u) ? 1 : 0;
}

// ---------------------------------------------------------------------------
// Converters: fp32 -> (hi, lo) bf16 split
// ---------------------------------------------------------------------------
__device__ __forceinline__ void split_bf16(float f, __nv_bfloat16& hi, __nv_bfloat16& lo)
{
    hi = __float2bfloat16_rn(f);
    lo = __float2bfloat16_rn(f - __bfloat162float(hi));
}

__global__ __launch_bounds__(256) void convert_x_kernel(const float* __restrict__ x)
{
    uint32_t idx = blockIdx.x * 256u + threadIdx.x;   // 2,097,152 total
    int m = idx >> 6, q = idx & 63;
    int b = m & 63, t = m >> 6;
    float4 v = *reinterpret_cast<const float4*>(x + ((size_t)b * 512 + t) * 256 + q * 4);
    __nv_bfloat16 h0, h1, h2, h3, l0, l1, l2, l3;
    split_bf16(v.x, h0, l0);
    split_bf16(v.y, h1, l1);
    split_bf16(v.z, h2, l2);
    split_bf16(v.w, h3, l3);
    __nv_bfloat162 hp0(h0, h1), hp1(h2, h3), lp0(l0, l1), lp1(l2, l3);
    uint2 hv, lv;
    hv.x = *reinterpret_cast<uint32_t*>(&hp0);
    hv.y = *reinterpret_cast<uint32_t*>(&hp1);
    lv.x = *reinterpret_cast<uint32_t*>(&lp0);
    lv.y = *reinterpret_cast<uint32_t*>(&lp1);
    *reinterpret_cast<uint2*>(g_Xhi + (size_t)m * 256 + q * 4) = hv;
    *reinterpret_cast<uint2*>(g_Xlo + (size_t)m * 256 + q * 4) = lv;
}

__global__ __launch_bounds__(256) void convert_w_kernel(
    const float* __restrict__ Wk_f, const float* __restrict__ Wk_b)
{
    uint32_t idx = blockIdx.x * 256u + threadIdx.x;   // 524,288 total
    int dir = idx >> 18;
    uint32_t rem = idx & 0x3FFFFu;
    int q = rem >> 8, k = rem & 255;
    int u = q >> 2, g = q & 3;
    float v = (dir ? Wk_b : Wk_f)[k * 1024 + g * 256 + u];
    __nv_bfloat16 hi, lo;
    split_bf16(v, hi, lo);
    g_Whi[idx] = hi;
    g_Wlo[idx] = lo;
}

// ---------------------------------------------------------------------------
// Input GEMM via mma.sync bf16 split-3 (proven: ~255us, tensor 67%)
// ---------------------------------------------------------------------------
#define GEMM_STAGE_BYTES 65536
#define GEMM_SMEM_BYTES  (2 * GEMM_STAGE_BYTES + 1024)

__global__ __launch_bounds__(256, 1) void gemm_mma_kernel(
    const float* __restrict__ b_f, const float* __restrict__ b_b)
{
    extern __shared__ char smc[];
    char* stages = smc;
    float* bias_s = reinterpret_cast<float*>(smc + 2 * GEMM_STAGE_BYTES);
    const uint32_t st_u32 = smem_u32(stages);

    const int tid  = threadIdx.x;
    const int wid  = tid >> 5, lane = tid & 31;
    const int wm   = wid & 3, wn = wid >> 2;
    const int mt   = blockIdx.x * 128;
    const int nt   = blockIdx.y;
    const int dir  = nt >> 3;
    const int q0   = (nt & 7) * 128;

    if (tid < 128) {
        const int q = q0 + tid;
        bias_s[tid] = (dir ? b_b : b_f)[(q & 3) * 256 + (q >> 2)];
    }

    const char* srcs[4] = {
        reinterpret_cast<const char*>(g_Xhi),
        reinterpret_cast<const char*>(g_Xlo),
        reinterpret_cast<const char*>(g_Whi),
        reinterpret_cast<const char*>(g_Wlo)
    };

    auto load_chunk = [&](int c, int s) {
        const uint32_t sb = st_u32 + (uint32_t)s * GEMM_STAGE_BYTES;
        const int koff = c * 128;
#pragma unroll
        for (int it = 0; it < 16; it++) {
            const int idx    = it * 256 + tid;
            const int region = idx >> 10;
            const int r      = (idx >> 3) & 127;
            const int q4     = idx & 7;
            const int grow   = (region < 2) ? (mt + r) : (dir * 1024 + q0 + r);
            const char* src  = srcs[region] + (size_t)grow * 512 + koff + q4 * 16;
            const uint32_t dst = sb + region * 16384 + r * 128
                               + (((uint32_t)q4 * 16) ^ (((uint32_t)(r & 7)) * 16));
            CP_ASYNC16(dst, src);
        }
    };

    const int grp = lane >> 3, lr = lane & 7;
    const uint32_t xr16 = (uint32_t)lr * 16;
    const uint32_t koffA = (uint32_t)(grp >> 1) * 16;
    const uint32_t koffB = (uint32_t)(grp & 1) * 16;
    uint32_t baseA[2], baseB[4];
#pragma unroll
    for (int i = 0; i < 2; i++) {
        const int rowA = wm * 32 + i * 16 + lr + (grp & 1) * 8;
        baseA[i] = (uint32_t)rowA * 128;
    }
#pragma unroll
    for (int j2 = 0; j2 < 4; j2++) {
        const int rowB = wn * 64 + j2 * 16 + lr + (grp >> 1) * 8;
        baseB[j2] = (uint32_t)rowB * 128;
    }

    float acc[2][8][4];
#pragma unroll
    for (int i = 0; i < 2; i++)
#pragma unroll
        for (int j = 0; j < 8; j++)
#pragma unroll
            for (int v = 0; v < 4; v++) acc[i][j][v] = 0.f;

    load_chunk(0, 0);
    CP_ASYNC_COMMIT();

#pragma unroll
    for (int c = 0; c < 4; c++) {
        if (c < 3) { load_chunk(c + 1, (c + 1) & 1); CP_ASYNC_COMMIT(); }
        if (c < 3) CP_ASYNC_WAIT(1); else CP_ASYNC_WAIT(0);
        __syncthreads();

        const uint32_t sb = st_u32 + (uint32_t)(c & 1) * GEMM_STAGE_BYTES;
        const uint32_t Ah = sb, Al = sb + 16384, Bh = sb + 32768, Bl = sb + 49152;

#pragma unroll
        for (int ks = 0; ks < 4; ks++) {
            const uint32_t offA = (((uint32_t)ks * 32) + koffA) ^ xr16;
            const uint32_t offB = (((uint32_t)ks * 32) + koffB) ^ xr16;
            uint32_t ah[2][4], al[2][4], bh[4][4], bl[4][4];
#pragma unroll
            for (int i = 0; i < 2; i++) {
                ldm4(ah[i], Ah + baseA[i] + offA);
                ldm4(al[i], Al + baseA[i] + offA);
            }
#pragma unroll
            for (int j2 = 0; j2 < 4; j2++) {
                ldm4(bh[j2], Bh + baseB[j2] + offB);
                ldm4(bl[j2], Bl + baseB[j2] + offB);
            }
#pragma unroll
            for (int i = 0; i < 2; i++)
#pragma unroll
                for (int j = 0; j < 8; j++) {
                    const int j2 = j >> 1, sel = (j & 1) * 2;
                    mma16816(acc[i][j], ah[i], bh[j2][sel], bh[j2][sel + 1]);
                    mma16816(acc[i][j], ah[i], bl[j2][sel], bl[j2][sel + 1]);
                    mma16816(acc[i][j], al[i], bh[j2][sel], bh[j2][sel + 1]);
                }
        }
        __syncthreads();
    }

    const int mrow0 = mt + wm * 32 + (lane >> 2);
    const int qcol0 = q0 + wn * 64 + (lane & 3) * 2;
#pragma unroll
    for (int i = 0; i < 2; i++) {
#pragma unroll
        for (int j = 0; j < 8; j++) {
            const int q  = qcol0 + j * 8;
            const float bx = bias_s[q - q0], by = bias_s[q - q0 + 1];
#pragma unroll
            for (int half = 0; half < 2; half++) {
                const int m  = mrow0 + i * 16 + half * 8;
                const int bb = m & 63, tt = m >> 6;
                float2 v;
                v.x = acc[i][j][half * 2 + 0] + bx;
                v.y = acc[i][j][half * 2 + 1] + by;
                *reinterpret_cast<float2*>(
                    g_Z + (((size_t)dir * 512 + tt) * 64 + bb) * 1024 + q) = v;
            }
        }
    }
}

// ---------------------------------------------------------------------------
// Recurrence v5 — tensor-core, mbarrier ring, direct bf16 DSMEM broadcast.
// 128 CTAs = 2 dirs x 8 batch-groups x 8 cluster ranks (cluster of 8).
// 512 threads (16 warps). Warp w owns n-cols [8w, 8w+8) = u {2w, 2w+1} x 4g.
// A tiles: [2 buf][hi|lo][16 rows][256 k bf16] (rows 8-15 zero); written
// remotely via packed bf16x2 st.shared::cluster from the gates phase.
// Sync: per-step mbarrier (8 cluster arrivals), parity = (step>>1)&1.
// SMEM: Whi 64K | Wlo 64K | A 32K | mask 4K | bars.
// ---------------------------------------------------------------------------
#define RV5_WHI   0
#define RV5_WLO   65536
#define RV5_A     131072
#define RV5_MASK  163840
#define RV5_BAR   167936
#define RV5_SMEM  168064

__device__ __forceinline__ uint32_t swz512(uint32_t row, uint32_t kb)
{
    return row * 512 + (kb & 0x180u) + ((kb & 0x70u) ^ ((row & 7u) << 4)) + (kb & 0xFu);
}

__global__ void __cluster_dims__(8, 1, 1) __launch_bounds__(512, 1)
lstm_rec_kernel(const float* __restrict__ Wr_f, const float* __restrict__ Wr_b,
                float* __restrict__ out)
{
    extern __shared__ char smr[];
    const uint32_t sbase = smem_u32(smr);
    unsigned char* m_s = reinterpret_cast<unsigned char*>(smr + RV5_MASK);

    const int tid  = threadIdx.x;
    const int bx   = blockIdx.x;
    const int dir  = bx >> 6;
    const int rank = bx & 7;
    const int bg   = (bx & 63) >> 3;
    const int w    = tid >> 5, lane = tid & 31;
    const int qh   = lane & 3;
    const int b    = lane >> 2;
    const int lr   = lane & 7, mg = lane >> 3;

    const int u_l  = 2 * w + (qh >> 1);
    const int ug   = (rank << 5) + u_l;
    const int ug_e = (rank << 5) + 2 * w;           // even u of this warp's pair
    const int b_global = (bg << 3) + b;

    // --- one-time init: Wr slice -> bf16 hi/lo (SW swizzled) --------------
    const float* Wr = dir ? Wr_b : Wr_f;
    for (int i = tid; i < 32768; i += 512) {
        const int n = i & 127;                      // n = u_local*4 + gate
        const int k = i >> 7;
        const float v = __ldg(&Wr[k * 1024 + (n & 3) * 256 + (rank << 5) + (n >> 2)]);
        __nv_bfloat16 hi, lo;
        split_bf16(v, hi, lo);
        const uint32_t off = swz512((uint32_t)n, (uint32_t)(k * 2));
        *reinterpret_cast<__nv_bfloat16*>(smr + RV5_WHI + off) = hi;
        *reinterpret_cast<__nv_bfloat16*>(smr + RV5_WLO + off) = lo;
    }
    // Zero A (both buffers, hi+lo): 32 KB
    for (int i = tid; i < 2048; i += 512)
        reinterpret_cast<float4*>(smr + RV5_A)[i] = make_float4(0.f, 0.f, 0.f, 0.f);
    for (int i = tid; i < 8 * 512; i += 512)
        m_s[i] = g_mask[((bg << 3) + (i >> 9)) * 512 + (i & 511)];
    if (tid == 0) {
        MBARRIER_INIT(sbase + RV5_BAR, 8);
        MBARRIER_INIT(sbase + RV5_BAR + 8, 8);
    }
    __syncthreads();
    CLUSTER_SYNC();   // bars + zeroed A visible cluster-wide

    // Remote bar addresses (one per source thread tid<8) and pre-arm bar0
    uint32_t rbar = 0;
    if (tid < 8) {
        rbar = mapa_rank(sbase + RV5_BAR, (uint32_t)tid);
        MBAR_ARRIVE_REL_CLUSTER(rbar);              // pre-arm buffer 0
    }

    // Remote A-tile hi-word addresses (this thread's (b, u-pair) word), buf0.
    // hi at +0, lo at +8192, buf1 at +16384.
    const uint32_t aword = RV5_A + swz512((uint32_t)b, (uint32_t)(2 * ug_e));
    uint32_t rA[8];
#pragma unroll
    for (int r = 0; r < 8; r++) rA[r] = mapa_rank(sbase + aword, (uint32_t)r);

    // GEMM fragment bases
    const uint32_t swx  = (uint32_t)lr << 4;
    const uint32_t rowB = (uint32_t)((w << 3) + lr) * 512;
    const uint32_t bBh  = sbase + RV5_WHI + rowB;
    const uint32_t bBl  = sbase + RV5_WLO + rowB;
    const uint32_t aRow = (uint32_t)(lr + (mg & 1) * 8) * 512;
    const uint32_t koffA = (uint32_t)(mg >> 1) << 4;

    float cst = 0.f, hprev = 0.f, hlast = 0.f;

    const float4* Z4 = reinterpret_cast<const float4*>(g_Z);
    const int t0 = dir ? 511 : 0;
    float4 znext = __ldg(&Z4[(((size_t)dir * 512 + t0) * 64 + b_global) * 256 + ug]);

    for (int step = 0; step < 512; step++) {
        const int t   = dir ? (511 - step) : step;
        const int cur = step & 1;
        const uint32_t par = (uint32_t)(step >> 1) & 1u;

        MBAR_WAIT_ACQ_CLUSTER(sbase + RV5_BAR + cur * 8, par);

        const float4 zin = znext;
        if (step < 511) {
            const int tn = dir ? (510 - step) : (step + 1);
            znext = __ldg(&Z4[(((size_t)dir * 512 + tn) * 64 + b_global) * 256 + ug]);
        }

        // ---- tensor GEMM: warp w computes n-cols [8w, 8w+8) -------------
        const uint32_t aHi = sbase + RV5_A + (uint32_t)cur * 16384 + aRow;
        const uint32_t aLo = aHi + 8192;
        float hh[4] = {0.f, 0.f, 0.f, 0.f};
        float hl[4] = {0.f, 0.f, 0.f, 0.f};
        float lh[4] = {0.f, 0.f, 0.f, 0.f};
#pragma unroll
        for (int kt2 = 0; kt2 < 8; kt2++) {
            const uint32_t kbB = (uint32_t)kt2 * 64 + ((uint32_t)mg << 4);
            const uint32_t offB = (kbB & 0x180u) + ((kbB & 0x70u) ^ swx);
            uint32_t bh[4], bl[4];
            ldm4(bh, bBh + offB);
            ldm4(bl, bBl + offB);
#pragma unroll
            for (int sub = 0; sub < 2; sub++) {
                const uint32_t kbA = (uint32_t)kt2 * 64 + (uint32_t)sub * 32 + koffA;
                const uint32_t offA = (kbA & 0x180u) + ((kbA & 0x70u) ^ swx);
                uint32_t ah[4], al[4];
                ldm4(ah, aHi + offA);
                ldm4(al, aLo + offA);
                mma16816(hh, ah, bh[sub * 2], bh[sub * 2 + 1]);
                mma16816(hl, ah, bl[sub * 2], bl[sub * 2 + 1]);
                mma16816(lh, al, bh[sub * 2], bh[sub * 2 + 1]);
            }
        }
        const float c0 = hh[0] + hl[0] + lh[0];
        const float c1 = hh[1] + hl[1] + lh[1];

        // ---- gate assembly: lane-pair (qh xor 1) exchange ---------------
        const float o0 = __shfl_xor_sync(0xffffffffu, c0, 1);
        const float o1 = __shfl_xor_sync(0xffffffffu, c1, 1);
        const bool isCO = (qh & 1) != 0;       // odd qh lanes hold (c,o)
        float zi = (isCO ? o0 : c0) + zin.x;
        float zf = (isCO ? o1 : c1) + zin.y;
        float zc = (isCO ? c0 : o0) + zin.z;
        float zo = (isCO ? c1 : o1) + zin.w;

        const float gi = tanhf(zi);
        const float gf = tanhf(zf);
        const float gc = tanhf(zc);
        const float go = tanhf(zo);
        const float cn = fmaf(gf, cst, gi * gc);
        const float hn = go * tanhf(cn);

        const bool  mk = m_s[(b << 9) + t] != 0;
        const float hv = mk ? hn : hprev;
        cst = mk ? cn : cst;
        hprev = hv;
        hlast = hv;

        if ((qh & 1) == 0)
            out[((size_t)b_global * 512 + t) * 512 + (dir << 8) + ug] = hv;

        // ---- broadcast h (bf16 hi/lo packed u32) to all 8 A[nxt] --------
        const float hvp = __shfl_xor_sync(0xffffffffu, hv, 2);  // partner u
        const uint32_t bo = (uint32_t)(cur ^ 1) * 16384;
        if (qh == 0) {
            __nv_bfloat16 he, le, ho, lo2;
            split_bf16(hv,  he, le);
            split_bf16(hvp, ho, lo2);
            const uint32_t wh = (uint32_t)*reinterpret_cast<unsigned short*>(&he)
                              | ((uint32_t)*reinterpret_cast<unsigned short*>(&ho) << 16);
            const uint32_t wl = (uint32_t)*reinterpret_cast<unsigned short*>(&le)
                              | ((uint32_t)*reinterpret_cast<unsigned short*>(&lo2) << 16);
#pragma unroll
            for (int r = 0; r < 8; r++) {
                ST_CLUSTER_U32(rA[r] + bo, wh);
                ST_CLUSTER_U32(rA[r] + bo + 8192, wl);
            }
        }
        __syncthreads();
        if (tid < 8)
            MBAR_ARRIVE_REL_CLUSTER(rbar + (cur ^ 1) * 8);
    }

    if ((qh & 1) == 0)
        out[16777216 + (size_t)b_global * 512 + (dir << 8) + ug] = hlast;

    CLUSTER_SYNC();   // no CTA exits while remote stores may target its SMEM
}

// ---------------------------------------------------------------------------
// Launch
// ---------------------------------------------------------------------------
extern "C" void kernel_launch(void* const* d_in, const int* in_sizes, int n_in,
                              void* d_out, int out_size)
{
    const float* x    = (const float*)d_in[0];
    const float* Wk_f = (const float*)d_in[1];
    const float* Wr_f = (const float*)d_in[2];
    const float* b_f  = (const float*)d_in[3];
    const float* Wk_b = (const float*)d_in[4];
    const float* Wr_b = (const float*)d_in[5];
    const float* b_b  = (const float*)d_in[6];
    float* out = (float*)d_out;

    mask_kernel<<<4096, 256>>>(x);
    convert_x_kernel<<<8192, 256>>>(x);
    convert_w_kernel<<<2048, 256>>>(Wk_f, Wk_b);

    cudaFuncSetAttribute(gemm_mma_kernel,
                         cudaFuncAttributeMaxDynamicSharedMemorySize, GEMM_SMEM_BYTES);
    dim3 gg(256, 16);
    gemm_mma_kernel<<<gg, 256, GEMM_SMEM_BYTES>>>(b_f, b_b);

    cudaFuncSetAttribute(lstm_rec_kernel,
                         cudaFuncAttributeMaxDynamicSharedMemorySize, RV5_SMEM);
    lstm_rec_kernel<<<128, 512, RV5_SMEM>>>(Wr_f, Wr_b, out);
}

// round 8
// speedup vs baseline: 1.0490x; 1.0490x over previous
#include <cuda_runtime.h>
#include <cuda_bf16.h>
#include <cstdint>
#include <cmath>

// Problem: B=64, T=512, E=256, U=256, bidirectional LSTM (all-tanh), mask carry.

// ---------------------------------------------------------------------------
// Device scratch
// ---------------------------------------------------------------------------
__device__ float g_Z[2ull * 512 * 64 * 1024];                  // [dir][t][b][u*4+g]
__device__ unsigned char g_mask[64 * 512];                     // [b][t]
__device__ __align__(16) __nv_bfloat16 g_Xhi[32768ull * 256];  // [m=t*64+b][k]
__device__ __align__(16) __nv_bfloat16 g_Xlo[32768ull * 256];
__device__ __align__(16) __nv_bfloat16 g_Whi[2ull * 1024 * 256]; // [dir][q=u*4+g][k]
__device__ __align__(16) __nv_bfloat16 g_Wlo[2ull * 1024 * 256];

// ---------------------------------------------------------------------------
// PTX helpers (family-level features only)
// ---------------------------------------------------------------------------
__device__ __forceinline__ uint32_t smem_u32(const void* p)
{
    uint32_t a;
    asm("{ .reg .u64 t; cvta.to.shared.u64 t, %1; cvt.u32.u64 %0, t; }"
        : "=r"(a) : "l"(p));
    return a;
}

#define CP_ASYNC16(dst, src) \
    asm volatile("cp.async.cg.shared.global [%0], [%1], 16;" \
                 :: "r"(dst), "l"(src) : "memory")
#define CP_ASYNC_COMMIT() asm volatile("cp.async.commit_group;" ::: "memory")
#define CP_ASYNC_WAIT(n)  asm volatile("cp.async.wait_group %0;" :: "n"(n) : "memory")

__device__ __forceinline__ void ldm4(uint32_t* r, uint32_t addr)
{
    asm volatile("ldmatrix.sync.aligned.m8n8.x4.shared.b16 {%0,%1,%2,%3}, [%4];"
                 : "=r"(r[0]), "=r"(r[1]), "=r"(r[2]), "=r"(r[3]) : "r"(addr));
}

__device__ __forceinline__ void mma16816(float* c, const uint32_t* a,
                                         uint32_t b0, uint32_t b1)
{
    asm volatile(
        "mma.sync.aligned.m16n8k16.row.col.f32.bf16.bf16.f32 "
        "{%0,%1,%2,%3}, {%4,%5,%6,%7}, {%8,%9}, {%0,%1,%2,%3};"
        : "+f"(c[0]), "+f"(c[1]), "+f"(c[2]), "+f"(c[3])
        : "r"(a[0]), "r"(a[1]), "r"(a[2]), "r"(a[3]), "r"(b0), "r"(b1));
}

__device__ __forceinline__ uint32_t mapa_rank(uint32_t addr, uint32_t rank)
{
    uint32_t r;
    asm("mapa.shared::cluster.u32 %0, %1, %2;" : "=r"(r) : "r"(addr), "r"(rank));
    return r;
}
#define ST_CLUSTER_U32(addr, v) \
    asm volatile("st.shared::cluster.u32 [%0], %1;" :: "r"(addr), "r"(v) : "memory")

#define CLUSTER_SYNC() do { \
    asm volatile("barrier.cluster.arrive.aligned;" ::: "memory"); \
    asm volatile("barrier.cluster.wait.aligned;"   ::: "memory"); \
} while (0)

// Fast tanh: 1 - 2/(e^{2x}+1)  (MUFU.EX2 + MUFU.RCP; rel err ~1e-6;
// saturates correctly at +/-1 for large |x|).
__device__ __forceinline__ float ftanh(float x)
{
    float e = __expf(2.f * x);
    return 1.f - __fdividef(2.f, e + 1.f);
}

// ---------------------------------------------------------------------------
// Mask kernel: mask[b][t] = any(x[b,t,:] != 0)
// ---------------------------------------------------------------------------
__global__ void mask_kernel(const float* __restrict__ x)
{
    int gw   = (blockIdx.x * blockDim.x + threadIdx.x) >> 5;
    int lane = threadIdx.x & 31;
    if (gw >= 64 * 512) return;
    const float4* p = reinterpret_cast<const float4*>(x + (size_t)gw * 256);
    float4 a = p[lane];
    float4 b = p[lane + 32];
    bool nz = (a.x != 0.f) || (a.y != 0.f) || (a.z != 0.f) || (a.w != 0.f) ||
              (b.x != 0.f) || (b.y != 0.f) || (b.z != 0.f) || (b.w != 0.f);
    unsigned m = __ballot_sync(0xffffffffu, nz);
    if (lane == 0) g_mask[gw] = (m != 0u) ? 1 : 0;
}

// ---------------------------------------------------------------------------
// Converters: fp32 -> (hi, lo) bf16 split
// ---------------------------------------------------------------------------
__device__ __forceinline__ void split_bf16(float f, __nv_bfloat16& hi, __nv_bfloat16& lo)
{
    hi = __float2bfloat16_rn(f);
    lo = __float2bfloat16_rn(f - __bfloat162float(hi));
}

__global__ __launch_bounds__(256) void convert_x_kernel(const float* __restrict__ x)
{
    uint32_t idx = blockIdx.x * 256u + threadIdx.x;   // 2,097,152 total
    int m = idx >> 6, q = idx & 63;
    int b = m & 63, t = m >> 6;
    float4 v = *reinterpret_cast<const float4*>(x + ((size_t)b * 512 + t) * 256 + q * 4);
    __nv_bfloat16 h0, h1, h2, h3, l0, l1, l2, l3;
    split_bf16(v.x, h0, l0);
    split_bf16(v.y, h1, l1);
    split_bf16(v.z, h2, l2);
    split_bf16(v.w, h3, l3);
    __nv_bfloat162 hp0(h0, h1), hp1(h2, h3), lp0(l0, l1), lp1(l2, l3);
    uint2 hv, lv;
    hv.x = *reinterpret_cast<uint32_t*>(&hp0);
    hv.y = *reinterpret_cast<uint32_t*>(&hp1);
    lv.x = *reinterpret_cast<uint32_t*>(&lp0);
    lv.y = *reinterpret_cast<uint32_t*>(&lp1);
    *reinterpret_cast<uint2*>(g_Xhi + (size_t)m * 256 + q * 4) = hv;
    *reinterpret_cast<uint2*>(g_Xlo + (size_t)m * 256 + q * 4) = lv;
}

__global__ __launch_bounds__(256) void convert_w_kernel(
    const float* __restrict__ Wk_f, const float* __restrict__ Wk_b)
{
    uint32_t idx = blockIdx.x * 256u + threadIdx.x;   // 524,288 total
    int dir = idx >> 18;
    uint32_t rem = idx & 0x3FFFFu;
    int q = rem >> 8, k = rem & 255;
    int u = q >> 2, g = q & 3;
    float v = (dir ? Wk_b : Wk_f)[k * 1024 + g * 256 + u];
    __nv_bfloat16 hi, lo;
    split_bf16(v, hi, lo);
    g_Whi[idx] = hi;
    g_Wlo[idx] = lo;
}

// ---------------------------------------------------------------------------
// Input GEMM via mma.sync bf16 split-3 (proven: ~255us, tensor 67%)
// ---------------------------------------------------------------------------
#define GEMM_STAGE_BYTES 65536
#define GEMM_SMEM_BYTES  (2 * GEMM_STAGE_BYTES + 1024)

__global__ __launch_bounds__(256, 1) void gemm_mma_kernel(
    const float* __restrict__ b_f, const float* __restrict__ b_b)
{
    extern __shared__ char smc[];
    char* stages = smc;
    float* bias_s = reinterpret_cast<float*>(smc + 2 * GEMM_STAGE_BYTES);
    const uint32_t st_u32 = smem_u32(stages);

    const int tid  = threadIdx.x;
    const int wid  = tid >> 5, lane = tid & 31;
    const int wm   = wid & 3, wn = wid >> 2;
    const int mt   = blockIdx.x * 128;
    const int nt   = blockIdx.y;
    const int dir  = nt >> 3;
    const int q0   = (nt & 7) * 128;

    if (tid < 128) {
        const int q = q0 + tid;
        bias_s[tid] = (dir ? b_b : b_f)[(q & 3) * 256 + (q >> 2)];
    }

    const char* srcs[4] = {
        reinterpret_cast<const char*>(g_Xhi),
        reinterpret_cast<const char*>(g_Xlo),
        reinterpret_cast<const char*>(g_Whi),
        reinterpret_cast<const char*>(g_Wlo)
    };

    auto load_chunk = [&](int c, int s) {
        const uint32_t sb = st_u32 + (uint32_t)s * GEMM_STAGE_BYTES;
        const int koff = c * 128;
#pragma unroll
        for (int it = 0; it < 16; it++) {
            const int idx    = it * 256 + tid;
            const int region = idx >> 10;
            const int r      = (idx >> 3) & 127;
            const int q4     = idx & 7;
            const int grow   = (region < 2) ? (mt + r) : (dir * 1024 + q0 + r);
            const char* src  = srcs[region] + (size_t)grow * 512 + koff + q4 * 16;
            const uint32_t dst = sb + region * 16384 + r * 128
                               + (((uint32_t)q4 * 16) ^ (((uint32_t)(r & 7)) * 16));
            CP_ASYNC16(dst, src);
        }
    };

    const int grp = lane >> 3, lr = lane & 7;
    const uint32_t xr16 = (uint32_t)lr * 16;
    const uint32_t koffA = (uint32_t)(grp >> 1) * 16;
    const uint32_t koffB = (uint32_t)(grp & 1) * 16;
    uint32_t baseA[2], baseB[4];
#pragma unroll
    for (int i = 0; i < 2; i++) {
        const int rowA = wm * 32 + i * 16 + lr + (grp & 1) * 8;
        baseA[i] = (uint32_t)rowA * 128;
    }
#pragma unroll
    for (int j2 = 0; j2 < 4; j2++) {
        const int rowB = wn * 64 + j2 * 16 + lr + (grp >> 1) * 8;
        baseB[j2] = (uint32_t)rowB * 128;
    }

    float acc[2][8][4];
#pragma unroll
    for (int i = 0; i < 2; i++)
#pragma unroll
        for (int j = 0; j < 8; j++)
#pragma unroll
            for (int v = 0; v < 4; v++) acc[i][j][v] = 0.f;

    load_chunk(0, 0);
    CP_ASYNC_COMMIT();

#pragma unroll
    for (int c = 0; c < 4; c++) {
        if (c < 3) { load_chunk(c + 1, (c + 1) & 1); CP_ASYNC_COMMIT(); }
        if (c < 3) CP_ASYNC_WAIT(1); else CP_ASYNC_WAIT(0);
        __syncthreads();

        const uint32_t sb = st_u32 + (uint32_t)(c & 1) * GEMM_STAGE_BYTES;
        const uint32_t Ah = sb, Al = sb + 16384, Bh = sb + 32768, Bl = sb + 49152;

#pragma unroll
        for (int ks = 0; ks < 4; ks++) {
            const uint32_t offA = (((uint32_t)ks * 32) + koffA) ^ xr16;
            const uint32_t offB = (((uint32_t)ks * 32) + koffB) ^ xr16;
            uint32_t ah[2][4], al[2][4], bh[4][4], bl[4][4];
#pragma unroll
            for (int i = 0; i < 2; i++) {
                ldm4(ah[i], Ah + baseA[i] + offA);
                ldm4(al[i], Al + baseA[i] + offA);
            }
#pragma unroll
            for (int j2 = 0; j2 < 4; j2++) {
                ldm4(bh[j2], Bh + baseB[j2] + offB);
                ldm4(bl[j2], Bl + baseB[j2] + offB);
            }
#pragma unroll
            for (int i = 0; i < 2; i++)
#pragma unroll
                for (int j = 0; j < 8; j++) {
                    const int j2 = j >> 1, sel = (j & 1) * 2;
                    mma16816(acc[i][j], ah[i], bh[j2][sel], bh[j2][sel + 1]);
                    mma16816(acc[i][j], ah[i], bl[j2][sel], bl[j2][sel + 1]);
                    mma16816(acc[i][j], al[i], bh[j2][sel], bh[j2][sel + 1]);
                }
        }
        __syncthreads();
    }

    const int mrow0 = mt + wm * 32 + (lane >> 2);
    const int qcol0 = q0 + wn * 64 + (lane & 3) * 2;
#pragma unroll
    for (int i = 0; i < 2; i++) {
#pragma unroll
        for (int j = 0; j < 8; j++) {
            const int q  = qcol0 + j * 8;
            const float bx = bias_s[q - q0], by = bias_s[q - q0 + 1];
#pragma unroll
            for (int half = 0; half < 2; half++) {
                const int m  = mrow0 + i * 16 + half * 8;
                const int bb = m & 63, tt = m >> 6;
                float2 v;
                v.x = acc[i][j][half * 2 + 0] + bx;
                v.y = acc[i][j][half * 2 + 1] + by;
                *reinterpret_cast<float2*>(
                    g_Z + (((size_t)dir * 512 + tt) * 64 + bb) * 1024 + q) = v;
            }
        }
    }
}

// ---------------------------------------------------------------------------
// Recurrence v6 — tensor-core, 512 threads, direct bf16 DSMEM broadcast,
// per-step barrier.cluster (the R6 sync that measured fastest).
// 128 CTAs = 2 dirs x 8 batch-groups x 8 cluster ranks (cluster of 8).
// Warp w (0..15) owns n-cols [8w, 8w+8) = u {2w, 2w+1} x 4 gates.
// A tiles: [2 buf][hi|lo][16 rows][256 k bf16] (rows 8-15 zero); written
// remotely via packed bf16x2 st.shared::cluster from the gates phase.
// SMEM: Whi 64K | Wlo 64K | A 32K | mask 4K.
// ---------------------------------------------------------------------------
#define RV6_WHI   0
#define RV6_WLO   65536
#define RV6_A     131072
#define RV6_MASK  163840
#define RV6_SMEM  167936

__device__ __forceinline__ uint32_t swz512(uint32_t row, uint32_t kb)
{
    return row * 512 + (kb & 0x180u) + ((kb & 0x70u) ^ ((row & 7u) << 4)) + (kb & 0xFu);
}

__global__ void __cluster_dims__(8, 1, 1) __launch_bounds__(512, 1)
lstm_rec_kernel(const float* __restrict__ Wr_f, const float* __restrict__ Wr_b,
                float* __restrict__ out)
{
    extern __shared__ char smr[];
    const uint32_t sbase = smem_u32(smr);
    unsigned char* m_s = reinterpret_cast<unsigned char*>(smr + RV6_MASK);

    const int tid  = threadIdx.x;
    const int bx   = blockIdx.x;
    const int dir  = bx >> 6;
    const int rank = bx & 7;
    const int bg   = (bx & 63) >> 3;
    const int w    = tid >> 5, lane = tid & 31;
    const int qh   = lane & 3;
    const int b    = lane >> 2;
    const int lr   = lane & 7, mg = lane >> 3;

    const int u_l  = 2 * w + (qh >> 1);
    const int ug   = (rank << 5) + u_l;
    const int ug_e = (rank << 5) + 2 * w;           // even u of this warp's pair
    const int b_global = (bg << 3) + b;

    // --- one-time init: Wr slice -> bf16 hi/lo (SW swizzled) --------------
    const float* Wr = dir ? Wr_b : Wr_f;
    for (int i = tid; i < 32768; i += 512) {
        const int n = i & 127;                      // n = u_local*4 + gate
        const int k = i >> 7;
        const float v = __ldg(&Wr[k * 1024 + (n & 3) * 256 + (rank << 5) + (n >> 2)]);
        __nv_bfloat16 hi, lo;
        split_bf16(v, hi, lo);
        const uint32_t off = swz512((uint32_t)n, (uint32_t)(k * 2));
        *reinterpret_cast<__nv_bfloat16*>(smr + RV6_WHI + off) = hi;
        *reinterpret_cast<__nv_bfloat16*>(smr + RV6_WLO + off) = lo;
    }
    // Zero A (both buffers, hi+lo): 32 KB
    for (int i = tid; i < 2048; i += 512)
        reinterpret_cast<float4*>(smr + RV6_A)[i] = make_float4(0.f, 0.f, 0.f, 0.f);
    for (int i = tid; i < 8 * 512; i += 512)
        m_s[i] = g_mask[((bg << 3) + (i >> 9)) * 512 + (i & 511)];
    __syncthreads();
    CLUSTER_SYNC();   // zeroed A + weights visible cluster-wide

    // Remote A-tile word addresses (this thread's (b, u-pair) word), buf0 base.
    // Store lanes: qh in {0, 1}; pair_u = (rank<<5) + 4? no: warp pair base
    // u {2w, 2w+1}; lanes qh==0 store word for that pair.
    const uint32_t aword = RV6_A + swz512((uint32_t)b, (uint32_t)(2 * ug_e));
    uint32_t rA[8];
#pragma unroll
    for (int r = 0; r < 8; r++) rA[r] = mapa_rank(sbase + aword, (uint32_t)r);

    // GEMM fragment bases
    const uint32_t swx  = (uint32_t)lr << 4;
    const uint32_t rowB = (uint32_t)((w << 3) + lr) * 512;
    const uint32_t bBh  = sbase + RV6_WHI + rowB;
    const uint32_t bBl  = sbase + RV6_WLO + rowB;
    const uint32_t aRow = (uint32_t)(lr + (mg & 1) * 8) * 512;
    const uint32_t koffA = (uint32_t)(mg >> 1) << 4;

    float cst = 0.f, hprev = 0.f, hlast = 0.f;

    const float4* Z4 = reinterpret_cast<const float4*>(g_Z);
    const int t0 = dir ? 511 : 0;
    float4 znext = __ldg(&Z4[(((size_t)dir * 512 + t0) * 64 + b_global) * 256 + ug]);

    for (int step = 0; step < 512; step++) {
        const int t   = dir ? (511 - step) : step;
        const int cur = step & 1;

        const float4 zin = znext;
        if (step < 511) {
            const int tn = dir ? (510 - step) : (step + 1);
            znext = __ldg(&Z4[(((size_t)dir * 512 + tn) * 64 + b_global) * 256 + ug]);
        }

        // ---- tensor GEMM: warp w computes n-cols [8w, 8w+8) -------------
        const uint32_t aHi = sbase + RV6_A + (uint32_t)cur * 16384 + aRow;
        const uint32_t aLo = aHi + 8192;
        float hh[4] = {0.f, 0.f, 0.f, 0.f};
        float hl[4] = {0.f, 0.f, 0.f, 0.f};
        float lh[4] = {0.f, 0.f, 0.f, 0.f};
#pragma unroll
        for (int kt2 = 0; kt2 < 8; kt2++) {
            const uint32_t kbB = (uint32_t)kt2 * 64 + ((uint32_t)mg << 4);
            const uint32_t offB = (kbB & 0x180u) + ((kbB & 0x70u) ^ swx);
            uint32_t bh[4], bl[4];
            ldm4(bh, bBh + offB);
            ldm4(bl, bBl + offB);
#pragma unroll
            for (int sub = 0; sub < 2; sub++) {
                const uint32_t kbA = (uint32_t)kt2 * 64 + (uint32_t)sub * 32 + koffA;
                const uint32_t offA = (kbA & 0x180u) + ((kbA & 0x70u) ^ swx);
                uint32_t ah[4], al[4];
                ldm4(ah, aHi + offA);
                ldm4(al, aLo + offA);
                mma16816(hh, ah, bh[sub * 2], bh[sub * 2 + 1]);
                mma16816(hl, ah, bl[sub * 2], bl[sub * 2 + 1]);
                mma16816(lh, al, bh[sub * 2], bh[sub * 2 + 1]);
            }
        }
        const float c0 = hh[0] + hl[0] + lh[0];
        const float c1 = hh[1] + hl[1] + lh[1];

        // ---- gate assembly: lane-pair (qh xor 1) exchange ---------------
        const float o0 = __shfl_xor_sync(0xffffffffu, c0, 1);
        const float o1 = __shfl_xor_sync(0xffffffffu, c1, 1);
        const bool isCO = (qh & 1) != 0;       // odd qh lanes hold (c,o)
        float zi = (isCO ? o0 : c0) + zin.x;
        float zf = (isCO ? o1 : c1) + zin.y;
        float zc = (isCO ? c0 : o0) + zin.z;
        float zo = (isCO ? c1 : o1) + zin.w;

        const float gi = ftanh(zi);
        const float gf = ftanh(zf);
        const float gc = ftanh(zc);
        const float go = ftanh(zo);
        const float cn = fmaf(gf, cst, gi * gc);
        const float hn = go * ftanh(cn);

        const bool  mk = m_s[(b << 9) + t] != 0;
        const float hv = mk ? hn : hprev;
        cst = mk ? cn : cst;
        hprev = hv;
        hlast = hv;

        if ((qh & 1) == 0)
            out[((size_t)b_global * 512 + t) * 512 + (dir << 8) + ug] = hv;

        // ---- broadcast h (bf16 hi/lo packed u32) to all 8 A[nxt] --------
        const float hvp = __shfl_xor_sync(0xffffffffu, hv, 2);  // partner u
        const uint32_t bo = (uint32_t)(cur ^ 1) * 16384;
        if (qh == 0) {
            __nv_bfloat16 he, le, ho, lo2;
            split_bf16(hv,  he, le);
            split_bf16(hvp, ho, lo2);
            const uint32_t wh = (uint32_t)*reinterpret_cast<unsigned short*>(&he)
                              | ((uint32_t)*reinterpret_cast<unsigned short*>(&ho) << 16);
            const uint32_t wl = (uint32_t)*reinterpret_cast<unsigned short*>(&le)
                              | ((uint32_t)*reinterpret_cast<unsigned short*>(&lo2) << 16);
#pragma unroll
            for (int r = 0; r < 8; r++) {
                ST_CLUSTER_U32(rA[r] + bo, wh);
                ST_CLUSTER_U32(rA[r] + bo + 8192, wl);
            }
        }

        CLUSTER_SYNC();   // releases remote stores, step boundary
    }

    if ((qh & 1) == 0)
        out[16777216 + (size_t)b_global * 512 + (dir << 8) + ug] = hlast;

    CLUSTER_SYNC();   // no CTA exits while remote stores may target its SMEM
}

// ---------------------------------------------------------------------------
// Launch
// ---------------------------------------------------------------------------
extern "C" void kernel_launch(void* const* d_in, const int* in_sizes, int n_in,
                              void* d_out, int out_size)
{
    const float* x    = (const float*)d_in[0];
    const float* Wk_f = (const float*)d_in[1];
    const float* Wr_f = (const float*)d_in[2];
    const float* b_f  = (const float*)d_in[3];
    const float* Wk_b = (const float*)d_in[4];
    const float* Wr_b = (const float*)d_in[5];
    const float* b_b  = (const float*)d_in[6];
    float* out = (float*)d_out;

    mask_kernel<<<4096, 256>>>(x);
    convert_x_kernel<<<8192, 256>>>(x);
    convert_w_kernel<<<2048, 256>>>(Wk_f, Wk_b);

    cudaFuncSetAttribute(gemm_mma_kernel,
                         cudaFuncAttributeMaxDynamicSharedMemorySize, GEMM_SMEM_BYTES);
    dim3 gg(256, 16);
    gemm_mma_kernel<<<gg, 256, GEMM_SMEM_BYTES>>>(b_f, b_b);

    cudaFuncSetAttribute(lstm_rec_kernel,
                         cudaFuncAttributeMaxDynamicSharedMemorySize, RV6_SMEM);
    lstm_rec_kernel<<<128, 512, RV6_SMEM>>>(Wr_f, Wr_b, out);
}

// round 9
// speedup vs baseline: 1.6564x; 1.5790x over previous
#include <cuda_runtime.h>
#include <cuda_bf16.h>
#include <cstdint>
#include <cmath>

// Problem: B=64, T=512, E=256, U=256, bidirectional LSTM (all-tanh), mask carry.

// ---------------------------------------------------------------------------
// Device scratch
// ---------------------------------------------------------------------------
__device__ float g_Z[2ull * 512 * 64 * 1024];                  // [dir][t][b][u*4+g]
__device__ unsigned char g_mask[64 * 512];                     // [b][t]
__device__ __align__(16) __nv_bfloat16 g_Xhi[32768ull * 256];  // [m=t*64+b][k]
__device__ __align__(16) __nv_bfloat16 g_Xlo[32768ull * 256];
__device__ __align__(16) __nv_bfloat16 g_Whi[2ull * 1024 * 256]; // [dir][q=u*4+g][k]
__device__ __align__(16) __nv_bfloat16 g_Wlo[2ull * 1024 * 256];

// ---------------------------------------------------------------------------
// PTX helpers (family-level features only)
// ---------------------------------------------------------------------------
__device__ __forceinline__ uint32_t smem_u32(const void* p)
{
    uint32_t a;
    asm("{ .reg .u64 t; cvta.to.shared.u64 t, %1; cvt.u32.u64 %0, t; }"
        : "=r"(a) : "l"(p));
    return a;
}

#define CP_ASYNC16(dst, src) \
    asm volatile("cp.async.cg.shared.global [%0], [%1], 16;" \
                 :: "r"(dst), "l"(src) : "memory")
#define CP_ASYNC_COMMIT() asm volatile("cp.async.commit_group;" ::: "memory")
#define CP_ASYNC_WAIT(n)  asm volatile("cp.async.wait_group %0;" :: "n"(n) : "memory")

__device__ __forceinline__ void ldm4(uint32_t* r, uint32_t addr)
{
    asm volatile("ldmatrix.sync.aligned.m8n8.x4.shared.b16 {%0,%1,%2,%3}, [%4];"
                 : "=r"(r[0]), "=r"(r[1]), "=r"(r[2]), "=r"(r[3]) : "r"(addr));
}

__device__ __forceinline__ void mma16816(float* c, const uint32_t* a,
                                         uint32_t b0, uint32_t b1)
{
    asm volatile(
        "mma.sync.aligned.m16n8k16.row.col.f32.bf16.bf16.f32 "
        "{%0,%1,%2,%3}, {%4,%5,%6,%7}, {%8,%9}, {%0,%1,%2,%3};"
        : "+f"(c[0]), "+f"(c[1]), "+f"(c[2]), "+f"(c[3])
        : "r"(a[0]), "r"(a[1]), "r"(a[2]), "r"(a[3]), "r"(b0), "r"(b1));
}

__device__ __forceinline__ uint32_t mapa_rank(uint32_t addr, uint32_t rank)
{
    uint32_t r;
    asm("mapa.shared::cluster.u32 %0, %1, %2;" : "=r"(r) : "r"(addr), "r"(rank));
    return r;
}
__device__ __forceinline__ void st_cluster_f32(uint32_t addr, float v)
{
    asm volatile("st.shared::cluster.f32 [%0], %1;" :: "r"(addr), "f"(v) : "memory");
}
#define CLUSTER_SYNC() do { \
    asm volatile("barrier.cluster.arrive.aligned;" ::: "memory"); \
    asm volatile("barrier.cluster.wait.aligned;"   ::: "memory"); \
} while (0)

// Fast tanh: 1 - 2/(e^{2x}+1)  (MUFU.EX2 + MUFU.RCP; rel err ~1e-6;
// saturates exactly at +/-1 for large |x|).
__device__ __forceinline__ float ftanh(float x)
{
    float e = __expf(2.f * x);
    return 1.f - __fdividef(2.f, e + 1.f);
}

// ---------------------------------------------------------------------------
// Mask kernel: mask[b][t] = any(x[b,t,:] != 0)
// ---------------------------------------------------------------------------
__global__ void mask_kernel(const float* __restrict__ x)
{
    int gw   = (blockIdx.x * blockDim.x + threadIdx.x) >> 5;
    int lane = threadIdx.x & 31;
    if (gw >= 64 * 512) return;
    const float4* p = reinterpret_cast<const float4*>(x + (size_t)gw * 256);
    float4 a = p[lane];
    float4 b = p[lane + 32];
    bool nz = (a.x != 0.f) || (a.y != 0.f) || (a.z != 0.f) || (a.w != 0.f) ||
              (b.x != 0.f) || (b.y != 0.f) || (b.z != 0.f) || (b.w != 0.f);
    unsigned m = __ballot_sync(0xffffffffu, nz);
    if (lane == 0) g_mask[gw] = (m != 0u) ? 1 : 0;
}

// ---------------------------------------------------------------------------
// Converters: fp32 -> (hi, lo) bf16 split
// ---------------------------------------------------------------------------
__device__ __forceinline__ void split_bf16(float f, __nv_bfloat16& hi, __nv_bfloat16& lo)
{
    hi = __float2bfloat16_rn(f);
    lo = __float2bfloat16_rn(f - __bfloat162float(hi));
}

__global__ __launch_bounds__(256) void convert_x_kernel(const float* __restrict__ x)
{
    uint32_t idx = blockIdx.x * 256u + threadIdx.x;   // 2,097,152 total
    int m = idx >> 6, q = idx & 63;
    int b = m & 63, t = m >> 6;
    float4 v = *reinterpret_cast<const float4*>(x + ((size_t)b * 512 + t) * 256 + q * 4);
    __nv_bfloat16 h0, h1, h2, h3, l0, l1, l2, l3;
    split_bf16(v.x, h0, l0);
    split_bf16(v.y, h1, l1);
    split_bf16(v.z, h2, l2);
    split_bf16(v.w, h3, l3);
    __nv_bfloat162 hp0(h0, h1), hp1(h2, h3), lp0(l0, l1), lp1(l2, l3);
    uint2 hv, lv;
    hv.x = *reinterpret_cast<uint32_t*>(&hp0);
    hv.y = *reinterpret_cast<uint32_t*>(&hp1);
    lv.x = *reinterpret_cast<uint32_t*>(&lp0);
    lv.y = *reinterpret_cast<uint32_t*>(&lp1);
    *reinterpret_cast<uint2*>(g_Xhi + (size_t)m * 256 + q * 4) = hv;
    *reinterpret_cast<uint2*>(g_Xlo + (size_t)m * 256 + q * 4) = lv;
}

__global__ __launch_bounds__(256) void convert_w_kernel(
    const float* __restrict__ Wk_f, const float* __restrict__ Wk_b)
{
    uint32_t idx = blockIdx.x * 256u + threadIdx.x;   // 524,288 total
    int dir = idx >> 18;
    uint32_t rem = idx & 0x3FFFFu;
    int q = rem >> 8, k = rem & 255;
    int u = q >> 2, g = q & 3;
    float v = (dir ? Wk_b : Wk_f)[k * 1024 + g * 256 + u];
    __nv_bfloat16 hi, lo;
    split_bf16(v, hi, lo);
    g_Whi[idx] = hi;
    g_Wlo[idx] = lo;
}

// ---------------------------------------------------------------------------
// Input GEMM via mma.sync bf16 split-3 (proven: ~255us, tensor 67%)
// ---------------------------------------------------------------------------
#define GEMM_STAGE_BYTES 65536
#define GEMM_SMEM_BYTES  (2 * GEMM_STAGE_BYTES + 1024)

__global__ __launch_bounds__(256, 1) void gemm_mma_kernel(
    const float* __restrict__ b_f, const float* __restrict__ b_b)
{
    extern __shared__ char smc[];
    char* stages = smc;
    float* bias_s = reinterpret_cast<float*>(smc + 2 * GEMM_STAGE_BYTES);
    const uint32_t st_u32 = smem_u32(stages);

    const int tid  = threadIdx.x;
    const int wid  = tid >> 5, lane = tid & 31;
    const int wm   = wid & 3, wn = wid >> 2;
    const int mt   = blockIdx.x * 128;
    const int nt   = blockIdx.y;
    const int dir  = nt >> 3;
    const int q0   = (nt & 7) * 128;

    if (tid < 128) {
        const int q = q0 + tid;
        bias_s[tid] = (dir ? b_b : b_f)[(q & 3) * 256 + (q >> 2)];
    }

    const char* srcs[4] = {
        reinterpret_cast<const char*>(g_Xhi),
        reinterpret_cast<const char*>(g_Xlo),
        reinterpret_cast<const char*>(g_Whi),
        reinterpret_cast<const char*>(g_Wlo)
    };

    auto load_chunk = [&](int c, int s) {
        const uint32_t sb = st_u32 + (uint32_t)s * GEMM_STAGE_BYTES;
        const int koff = c * 128;
#pragma unroll
        for (int it = 0; it < 16; it++) {
            const int idx    = it * 256 + tid;
            const int region = idx >> 10;
            const int r      = (idx >> 3) & 127;
            const int q4     = idx & 7;
            const int grow   = (region < 2) ? (mt + r) : (dir * 1024 + q0 + r);
            const char* src  = srcs[region] + (size_t)grow * 512 + koff + q4 * 16;
            const uint32_t dst = sb + region * 16384 + r * 128
                               + (((uint32_t)q4 * 16) ^ (((uint32_t)(r & 7)) * 16));
            CP_ASYNC16(dst, src);
        }
    };

    const int grp = lane >> 3, lr = lane & 7;
    const uint32_t xr16 = (uint32_t)lr * 16;
    const uint32_t koffA = (uint32_t)(grp >> 1) * 16;
    const uint32_t koffB = (uint32_t)(grp & 1) * 16;
    uint32_t baseA[2], baseB[4];
#pragma unroll
    for (int i = 0; i < 2; i++) {
        const int rowA = wm * 32 + i * 16 + lr + (grp & 1) * 8;
        baseA[i] = (uint32_t)rowA * 128;
    }
#pragma unroll
    for (int j2 = 0; j2 < 4; j2++) {
        const int rowB = wn * 64 + j2 * 16 + lr + (grp >> 1) * 8;
        baseB[j2] = (uint32_t)rowB * 128;
    }

    float acc[2][8][4];
#pragma unroll
    for (int i = 0; i < 2; i++)
#pragma unroll
        for (int j = 0; j < 8; j++)
#pragma unroll
            for (int v = 0; v < 4; v++) acc[i][j][v] = 0.f;

    load_chunk(0, 0);
    CP_ASYNC_COMMIT();

#pragma unroll
    for (int c = 0; c < 4; c++) {
        if (c < 3) { load_chunk(c + 1, (c + 1) & 1); CP_ASYNC_COMMIT(); }
        if (c < 3) CP_ASYNC_WAIT(1); else CP_ASYNC_WAIT(0);
        __syncthreads();

        const uint32_t sb = st_u32 + (uint32_t)(c & 1) * GEMM_STAGE_BYTES;
        const uint32_t Ah = sb, Al = sb + 16384, Bh = sb + 32768, Bl = sb + 49152;

#pragma unroll
        for (int ks = 0; ks < 4; ks++) {
            const uint32_t offA = (((uint32_t)ks * 32) + koffA) ^ xr16;
            const uint32_t offB = (((uint32_t)ks * 32) + koffB) ^ xr16;
            uint32_t ah[2][4], al[2][4], bh[4][4], bl[4][4];
#pragma unroll
            for (int i = 0; i < 2; i++) {
                ldm4(ah[i], Ah + baseA[i] + offA);
                ldm4(al[i], Al + baseA[i] + offA);
            }
#pragma unroll
            for (int j2 = 0; j2 < 4; j2++) {
                ldm4(bh[j2], Bh + baseB[j2] + offB);
                ldm4(bl[j2], Bl + baseB[j2] + offB);
            }
#pragma unroll
            for (int i = 0; i < 2; i++)
#pragma unroll
                for (int j = 0; j < 8; j++) {
                    const int j2 = j >> 1, sel = (j & 1) * 2;
                    mma16816(acc[i][j], ah[i], bh[j2][sel], bh[j2][sel + 1]);
                    mma16816(acc[i][j], ah[i], bl[j2][sel], bl[j2][sel + 1]);
                    mma16816(acc[i][j], al[i], bh[j2][sel], bh[j2][sel + 1]);
                }
        }
        __syncthreads();
    }

    const int mrow0 = mt + wm * 32 + (lane >> 2);
    const int qcol0 = q0 + wn * 64 + (lane & 3) * 2;
#pragma unroll
    for (int i = 0; i < 2; i++) {
#pragma unroll
        for (int j = 0; j < 8; j++) {
            const int q  = qcol0 + j * 8;
            const float bx = bias_s[q - q0], by = bias_s[q - q0 + 1];
#pragma unroll
            for (int half = 0; half < 2; half++) {
                const int m  = mrow0 + i * 16 + half * 8;
                const int bb = m & 63, tt = m >> 6;
                float2 v;
                v.x = acc[i][j][half * 2 + 0] + bx;
                v.y = acc[i][j][half * 2 + 1] + by;
                *reinterpret_cast<float2*>(
                    g_Z + (((size_t)dir * 512 + tt) * 64 + bb) * 1024 + q) = v;
            }
        }
    }
}

// ---------------------------------------------------------------------------
// Recurrence v7 — R6 structure (256 threads, convert phase, f32 h DSMEM
// broadcast, per-step barrier.cluster) + {ftanh, 6 acc chains, reg-carried h}.
// 128 CTAs = 2 dirs x 8 batch-groups x 8 cluster ranks (cluster of 8).
// SMEM: Whi 64K | Wlo 64K | Ahi 8K | Alo 8K | h_f 2x8x260 f32 | mask 4K.
// ---------------------------------------------------------------------------
#define RV4_WHI   0
#define RV4_WLO   65536
#define RV4_AHI   131072
#define RV4_ALO   139264
#define RV4_HF    147456
#define RV4_MASK  (RV4_HF + 2 * 8 * 260 * 4)   // 164096
#define RV4_SMEM  (RV4_MASK + 4096)            // 168192

__device__ __forceinline__ uint32_t swz512(uint32_t row, uint32_t kb)
{
    // row stride 512B, SW128 within each 128B chunk; kb multiple of 2.
    return row * 512 + (kb & 0x180u) + (((kb & 0x70u) ^ ((row & 7u) << 4))) + (kb & 0xFu);
}

__global__ void __cluster_dims__(8, 1, 1) __launch_bounds__(256, 1)
lstm_rec_kernel(const float* __restrict__ Wr_f, const float* __restrict__ Wr_b,
                float* __restrict__ out)
{
    extern __shared__ char smr[];
    const uint32_t sbase = smem_u32(smr);
    float* h_f = reinterpret_cast<float*>(smr + RV4_HF);    // [2][8 b][260] (k=ug)
    unsigned char* m_s = reinterpret_cast<unsigned char*>(smr + RV4_MASK);

    const int tid  = threadIdx.x;
    const int bx   = blockIdx.x;
    const int dir  = bx >> 6;
    const int rank = bx & 7;
    const int bg   = (bx & 63) >> 3;
    const int w    = tid >> 5, lane = tid & 31;
    const int b    = lane >> 2;                 // batch row 0..7
    const int q    = lane & 3;
    const int mg   = lane >> 3, lr = lane & 7;  // ldmatrix groups

    // Per-lane owned (b, u) after gate shuffle:
    const int u_l  = 4 * w + (q >> 1) + 2 * (q & 1);
    const int ug   = (rank << 5) + u_l;
    const int b_global = (bg << 3) + b;

    // --- init: Wr slice -> bf16 hi/lo SMEM (one-time) ---------------------
    const float* Wr = dir ? Wr_b : Wr_f;
    for (int i = tid; i < 32768; i += 256) {
        const int n = i & 127;                  // n = u_local*4 + gate
        const int k = i >> 7;
        const float v = __ldg(&Wr[k * 1024 + (n & 3) * 256 + (rank << 5) + (n >> 2)]);
        __nv_bfloat16 hi, lo;
        split_bf16(v, hi, lo);
        const uint32_t off = swz512((uint32_t)n, (uint32_t)(k * 2));
        *reinterpret_cast<__nv_bfloat16*>(smr + RV4_WHI + off) = hi;
        *reinterpret_cast<__nv_bfloat16*>(smr + RV4_WLO + off) = lo;
    }
    // Zero A (hi+lo contiguous: 16 KB) — rows 8-15 stay zero forever
    for (int i = tid; i < 1024; i += 256)
        reinterpret_cast<float4*>(smr + RV4_AHI)[i] = make_float4(0.f, 0.f, 0.f, 0.f);
    for (int i = tid; i < 2 * 8 * 260; i += 256) h_f[i] = 0.f;
    for (int i = tid; i < 8 * 512; i += 256)
        m_s[i] = g_mask[((bg << 3) + (i >> 9)) * 512 + (i & 511)];

    // DSMEM broadcast addresses (both h buffers x 8 ranks)
    const uint32_t hf0 = sbase + RV4_HF + ((uint32_t)(b * 260 + ug) << 2);
    const uint32_t hf1 = hf0 + 8 * 260 * 4;
    uint32_t ra0[8], ra1[8];
#pragma unroll
    for (int r = 0; r < 8; r++) { ra0[r] = mapa_rank(hf0, r); ra1[r] = mapa_rank(hf1, r); }

    CLUSTER_SYNC();

    // ldmatrix address bases (constant over steps except k-tile offset)
    const uint32_t rowA = (uint32_t)(lr + (mg & 1) * 8);
    const uint32_t koffA = (uint32_t)((mg >> 1) * 16);
    const uint32_t rowB = (uint32_t)(w * 16 + lr + (mg >> 1) * 8);
    const uint32_t koffB = (uint32_t)((mg & 1) * 16);
    const uint32_t swA = (uint32_t)lr << 4;
    const uint32_t baseAhi = sbase + RV4_AHI + rowA * 512;
    const uint32_t baseAlo = sbase + RV4_ALO + rowA * 512;
    const uint32_t baseBhi = sbase + RV4_WHI + rowB * 512;
    const uint32_t baseBlo = sbase + RV4_WLO + rowB * 512;

    // Conversion-phase mapping: warp cb converts h row cb (b = warp id)
    const int cb = tid >> 5;
    const int ck = (tid & 31) * 8;              // 8 k values per thread
    const uint32_t convOff = swz512((uint32_t)cb, (uint32_t)(tid & 31) * 16);

    float cst = 0.f, hprev = 0.f, hlast = 0.f;
    int cur = 0;

    const float4* Z4 = reinterpret_cast<const float4*>(g_Z);
    const int t0 = dir ? 511 : 0;
    float4 znext = __ldg(&Z4[(((size_t)dir * 512 + t0) * 64 + b_global) * 256 + ug]);

    for (int step = 0; step < 512; step++) {
        const int t = dir ? (511 - step) : step;
        const float4 zin = znext;
        if (step < 511) {
            const int tn = dir ? (510 - step) : (step + 1);
            znext = __ldg(&Z4[(((size_t)dir * 512 + tn) * 64 + b_global) * 256 + ug]);
        }

        // ---- convert h_f[cur] -> A smem (bf16 hi/lo, swizzled) ----------
        {
            const float* hr = h_f + (cur * 8 + cb) * 260 + ck;
            float4 p0 = *reinterpret_cast<const float4*>(hr);
            float4 p1 = *reinterpret_cast<const float4*>(hr + 4);
            __nv_bfloat16 h8[8], l8[8];
            split_bf16(p0.x, h8[0], l8[0]);
            split_bf16(p0.y, h8[1], l8[1]);
            split_bf16(p0.z, h8[2], l8[2]);
            split_bf16(p0.w, h8[3], l8[3]);
            split_bf16(p1.x, h8[4], l8[4]);
            split_bf16(p1.y, h8[5], l8[5]);
            split_bf16(p1.z, h8[6], l8[6]);
            split_bf16(p1.w, h8[7], l8[7]);
            *reinterpret_cast<uint4*>(smr + RV4_AHI + convOff) =
                *reinterpret_cast<uint4*>(h8);
            *reinterpret_cast<uint4*>(smr + RV4_ALO + convOff) =
                *reinterpret_cast<uint4*>(l8);
        }
        __syncthreads();

        // ---- tensor GEMM: C[16, 16 cols] for warp w ---------------------
        // 6 independent accumulator chains (3 split terms x 2 n-halves).
        float a0[4] = {0.f, 0.f, 0.f, 0.f};
        float b0[4] = {0.f, 0.f, 0.f, 0.f};
        float c0v[4] = {0.f, 0.f, 0.f, 0.f};
        float a1[4] = {0.f, 0.f, 0.f, 0.f};
        float b1[4] = {0.f, 0.f, 0.f, 0.f};
        float c1v[4] = {0.f, 0.f, 0.f, 0.f};
#pragma unroll
        for (int kt = 0; kt < 16; kt++) {
            const uint32_t kbA = (uint32_t)kt * 32 + koffA;
            const uint32_t kbB = (uint32_t)kt * 32 + koffB;
            const uint32_t offA = (kbA & 0x180u) + ((kbA & 0x70u) ^ swA);
            const uint32_t offB = (kbB & 0x180u) + ((kbB & 0x70u) ^ swA);
            uint32_t ah[4], al[4], bh[4], bl[4];
            ldm4(ah, baseAhi + offA);
            ldm4(al, baseAlo + offA);
            ldm4(bh, baseBhi + offB);
            ldm4(bl, baseBlo + offB);
            mma16816(a0, ah, bh[0], bh[1]);
            mma16816(b0, ah, bl[0], bl[1]);
            mma16816(c0v, al, bh[0], bh[1]);
            mma16816(a1, ah, bh[2], bh[3]);
            mma16816(b1, ah, bl[2], bl[3]);
            mma16816(c1v, al, bh[2], bh[3]);
        }
        float acc0[2], acc1[2];
        acc0[0] = a0[0] + b0[0] + c0v[0];
        acc0[1] = a0[1] + b0[1] + c0v[1];
        acc1[0] = a1[0] + b1[0] + c1v[0];
        acc1[1] = a1[1] + b1[1] + c1v[1];

        // ---- gate assembly: lane pair (q even/odd) exchange -------------
        const bool odd = (q & 1) != 0;
        const float s0 = odd ? acc0[0] : acc1[0];
        const float s1 = odd ? acc0[1] : acc1[1];
        const float r0 = __shfl_xor_sync(0xffffffffu, s0, 1);
        const float r1 = __shfl_xor_sync(0xffffffffu, s1, 1);
        float zi = odd ? r0 : acc0[0];
        float zf = odd ? r1 : acc0[1];
        float zc = odd ? acc1[0] : r0;
        float zo = odd ? acc1[1] : r1;
        zi += zin.x; zf += zin.y; zc += zin.z; zo += zin.w;

        const float gi = ftanh(zi);
        const float gf = ftanh(zf);
        const float gc = ftanh(zc);
        const float go = ftanh(zo);
        const float cn = fmaf(gf, cst, gi * gc);
        const float hn = go * ftanh(cn);

        const bool  mk = m_s[(b << 9) + t] != 0;
        const float hv = mk ? hn : hprev;
        cst = mk ? cn : cst;
        hprev = hv;
        hlast = hv;

        out[((size_t)b_global * 512 + t) * 512 + (dir << 8) + ug] = hv;

        // ---- broadcast h to all 8 CTAs' next buffer ---------------------
        const int nxt = cur ^ 1;
#pragma unroll
        for (int r = 0; r < 8; r++)
            st_cluster_f32(nxt ? ra1[r] : ra0[r], hv);

        CLUSTER_SYNC();
        cur = nxt;
    }

    out[16777216 + (size_t)b_global * 512 + (dir << 8) + ug] = hlast;
}

// ---------------------------------------------------------------------------
// Launch
// ---------------------------------------------------------------------------
extern "C" void kernel_launch(void* const* d_in, const int* in_sizes, int n_in,
                              void* d_out, int out_size)
{
    const float* x    = (const float*)d_in[0];
    const float* Wk_f = (const float*)d_in[1];
    const float* Wr_f = (const float*)d_in[2];
    const float* b_f  = (const float*)d_in[3];
    const float* Wk_b = (const float*)d_in[4];
    const float* Wr_b = (const float*)d_in[5];
    const float* b_b  = (const float*)d_in[6];
    float* out = (float*)d_out;

    mask_kernel<<<4096, 256>>>(x);
    convert_x_kernel<<<8192, 256>>>(x);
    convert_w_kernel<<<2048, 256>>>(Wk_f, Wk_b);

    cudaFuncSetAttribute(gemm_mma_kernel,
                         cudaFuncAttributeMaxDynamicSharedMemorySize, GEMM_SMEM_BYTES);
    dim3 gg(256, 16);
    gemm_mma_kernel<<<gg, 256, GEMM_SMEM_BYTES>>>(b_f, b_b);

    cudaFuncSetAttribute(lstm_rec_kernel,
                         cudaFuncAttributeMaxDynamicSharedMemorySize, RV4_SMEM);
    lstm_rec_kernel<<<128, 256, RV4_SMEM>>>(Wr_f, Wr_b, out);
}

// round 10
// speedup vs baseline: 1.8885x; 1.1401x over previous
#include <cuda_runtime.h>
#include <cuda_bf16.h>
#include <cstdint>
#include <cmath>

// Problem: B=64, T=512, E=256, U=256, bidirectional LSTM (all-tanh), mask carry.

// ---------------------------------------------------------------------------
// Device scratch
// ---------------------------------------------------------------------------
__device__ float g_Z[2ull * 512 * 64 * 1024];                  // [dir][t][b][u*4+g]
__device__ unsigned char g_mask[64 * 512];                     // [b][t]
__device__ __align__(16) __nv_bfloat16 g_Xhi[32768ull * 256];  // [m=t*64+b][k]
__device__ __align__(16) __nv_bfloat16 g_Xlo[32768ull * 256];
__device__ __align__(16) __nv_bfloat16 g_Whi[2ull * 1024 * 256]; // [dir][q=u*4+g][k]
__device__ __align__(16) __nv_bfloat16 g_Wlo[2ull * 1024 * 256];

// ---------------------------------------------------------------------------
// PTX helpers (family-level features only)
// ---------------------------------------------------------------------------
__device__ __forceinline__ uint32_t smem_u32(const void* p)
{
    uint32_t a;
    asm("{ .reg .u64 t; cvta.to.shared.u64 t, %1; cvt.u32.u64 %0, t; }"
        : "=r"(a) : "l"(p));
    return a;
}

#define CP_ASYNC16(dst, src) \
    asm volatile("cp.async.cg.shared.global [%0], [%1], 16;" \
                 :: "r"(dst), "l"(src) : "memory")
#define CP_ASYNC_COMMIT() asm volatile("cp.async.commit_group;" ::: "memory")
#define CP_ASYNC_WAIT(n)  asm volatile("cp.async.wait_group %0;" :: "n"(n) : "memory")

__device__ __forceinline__ void ldm4(uint32_t* r, uint32_t addr)
{
    asm volatile("ldmatrix.sync.aligned.m8n8.x4.shared.b16 {%0,%1,%2,%3}, [%4];"
                 : "=r"(r[0]), "=r"(r[1]), "=r"(r[2]), "=r"(r[3]) : "r"(addr));
}

__device__ __forceinline__ void mma16816(float* c, const uint32_t* a,
                                         uint32_t b0, uint32_t b1)
{
    asm volatile(
        "mma.sync.aligned.m16n8k16.row.col.f32.bf16.bf16.f32 "
        "{%0,%1,%2,%3}, {%4,%5,%6,%7}, {%8,%9}, {%0,%1,%2,%3};"
        : "+f"(c[0]), "+f"(c[1]), "+f"(c[2]), "+f"(c[3])
        : "r"(a[0]), "r"(a[1]), "r"(a[2]), "r"(a[3]), "r"(b0), "r"(b1));
}

__device__ __forceinline__ uint32_t mapa_rank(uint32_t addr, uint32_t rank)
{
    uint32_t r;
    asm("mapa.shared::cluster.u32 %0, %1, %2;" : "=r"(r) : "r"(addr), "r"(rank));
    return r;
}
#define ST_CLUSTER_U32(addr, v) \
    asm volatile("st.shared::cluster.u32 [%0], %1;" :: "r"(addr), "r"(v) : "memory")

#define MBARRIER_INIT(addr, count) \
    asm volatile("mbarrier.init.shared.b64 [%0], %1;" \
                 :: "r"((uint32_t)(addr)), "r"((uint32_t)(count)) : "memory")
#define MBAR_ARRIVE_REL_CLUSTER(addr) \
    asm volatile("mbarrier.arrive.release.cluster.shared::cluster.b64 _, [%0];" \
                 :: "r"((uint32_t)(addr)) : "memory")

#define MBAR_WAIT_ACQ_CLUSTER(mbar, parity) do { \
    uint32_t _m = (uint32_t)(mbar); \
    uint32_t _p = (uint32_t)(parity); \
    uint32_t _done; \
    asm volatile( \
        "{\n\t.reg .pred p;\n\t" \
        "mbarrier.try_wait.parity.acquire.cluster.shared::cta.b64 p, [%1], %2;\n\t" \
        "selp.b32 %0, 1, 0, p;\n\t}" \
        : "=r"(_done) : "r"(_m), "r"(_p) : "memory"); \
    if (!_done) { \
        asm volatile( \
            "{\n\t.reg .pred P1;\n\t" \
            "WL_%=:\n\t" \
            "mbarrier.try_wait.parity.acquire.cluster.shared::cta.b64 P1, [%0], %1, 0x989680;\n\t" \
            "@P1 bra.uni WD_%=;\n\t" \
            "bra.uni WL_%=;\n\t" \
            "WD_%=:\n\t}" \
            :: "r"(_m), "r"(_p) : "memory"); \
    } \
} while (0)

#define CLUSTER_SYNC() do { \
    asm volatile("barrier.cluster.arrive.aligned;" ::: "memory"); \
    asm volatile("barrier.cluster.wait.aligned;"   ::: "memory"); \
} while (0)

// Fast tanh: 1 - 2/(e^{2x}+1)  (MUFU path; rel err ~1e-6, exact saturation).
__device__ __forceinline__ float ftanh(float x)
{
    float e = __expf(2.f * x);
    return 1.f - __fdividef(2.f, e + 1.f);
}

// ---------------------------------------------------------------------------
// Mask kernel: mask[b][t] = any(x[b,t,:] != 0)
// ---------------------------------------------------------------------------
__global__ void mask_kernel(const float* __restrict__ x)
{
    int gw   = (blockIdx.x * blockDim.x + threadIdx.x) >> 5;
    int lane = threadIdx.x & 31;
    if (gw >= 64 * 512) return;
    const float4* p = reinterpret_cast<const float4*>(x + (size_t)gw * 256);
    float4 a = p[lane];
    float4 b = p[lane + 32];
    bool nz = (a.x != 0.f) || (a.y != 0.f) || (a.z != 0.f) || (a.w != 0.f) ||
              (b.x != 0.f) || (b.y != 0.f) || (b.z != 0.f) || (b.w != 0.f);
    unsigned m = __ballot_sync(0xffffffffu, nz);
    if (lane == 0) g_mask[gw] = (m != 0u) ? 1 : 0;
}

// ---------------------------------------------------------------------------
// Converters: fp32 -> (hi, lo) bf16 split
// ---------------------------------------------------------------------------
__device__ __forceinline__ void split_bf16(float f, __nv_bfloat16& hi, __nv_bfloat16& lo)
{
    hi = __float2bfloat16_rn(f);
    lo = __float2bfloat16_rn(f - __bfloat162float(hi));
}

__global__ __launch_bounds__(256) void convert_x_kernel(const float* __restrict__ x)
{
    uint32_t idx = blockIdx.x * 256u + threadIdx.x;   // 2,097,152 total
    int m = idx >> 6, q = idx & 63;
    int b = m & 63, t = m >> 6;
    float4 v = *reinterpret_cast<const float4*>(x + ((size_t)b * 512 + t) * 256 + q * 4);
    __nv_bfloat16 h0, h1, h2, h3, l0, l1, l2, l3;
    split_bf16(v.x, h0, l0);
    split_bf16(v.y, h1, l1);
    split_bf16(v.z, h2, l2);
    split_bf16(v.w, h3, l3);
    __nv_bfloat162 hp0(h0, h1), hp1(h2, h3), lp0(l0, l1), lp1(l2, l3);
    uint2 hv, lv;
    hv.x = *reinterpret_cast<uint32_t*>(&hp0);
    hv.y = *reinterpret_cast<uint32_t*>(&hp1);
    lv.x = *reinterpret_cast<uint32_t*>(&lp0);
    lv.y = *reinterpret_cast<uint32_t*>(&lp1);
    *reinterpret_cast<uint2*>(g_Xhi + (size_t)m * 256 + q * 4) = hv;
    *reinterpret_cast<uint2*>(g_Xlo + (size_t)m * 256 + q * 4) = lv;
}

__global__ __launch_bounds__(256) void convert_w_kernel(
    const float* __restrict__ Wk_f, const float* __restrict__ Wk_b)
{
    uint32_t idx = blockIdx.x * 256u + threadIdx.x;   // 524,288 total
    int dir = idx >> 18;
    uint32_t rem = idx & 0x3FFFFu;
    int q = rem >> 8, k = rem & 255;
    int u = q >> 2, g = q & 3;
    float v = (dir ? Wk_b : Wk_f)[k * 1024 + g * 256 + u];
    __nv_bfloat16 hi, lo;
    split_bf16(v, hi, lo);
    g_Whi[idx] = hi;
    g_Wlo[idx] = lo;
}

// ---------------------------------------------------------------------------
// Input GEMM via mma.sync bf16 split-3 (proven: ~255us, tensor 67%)
// ---------------------------------------------------------------------------
#define GEMM_STAGE_BYTES 65536
#define GEMM_SMEM_BYTES  (2 * GEMM_STAGE_BYTES + 1024)

__global__ __launch_bounds__(256, 1) void gemm_mma_kernel(
    const float* __restrict__ b_f, const float* __restrict__ b_b)
{
    extern __shared__ char smc[];
    char* stages = smc;
    float* bias_s = reinterpret_cast<float*>(smc + 2 * GEMM_STAGE_BYTES);
    const uint32_t st_u32 = smem_u32(stages);

    const int tid  = threadIdx.x;
    const int wid  = tid >> 5, lane = tid & 31;
    const int wm   = wid & 3, wn = wid >> 2;
    const int mt   = blockIdx.x * 128;
    const int nt   = blockIdx.y;
    const int dir  = nt >> 3;
    const int q0   = (nt & 7) * 128;

    if (tid < 128) {
        const int q = q0 + tid;
        bias_s[tid] = (dir ? b_b : b_f)[(q & 3) * 256 + (q >> 2)];
    }

    const char* srcs[4] = {
        reinterpret_cast<const char*>(g_Xhi),
        reinterpret_cast<const char*>(g_Xlo),
        reinterpret_cast<const char*>(g_Whi),
        reinterpret_cast<const char*>(g_Wlo)
    };

    auto load_chunk = [&](int c, int s) {
        const uint32_t sb = st_u32 + (uint32_t)s * GEMM_STAGE_BYTES;
        const int koff = c * 128;
#pragma unroll
        for (int it = 0; it < 16; it++) {
            const int idx    = it * 256 + tid;
            const int region = idx >> 10;
            const int r      = (idx >> 3) & 127;
            const int q4     = idx & 7;
            const int grow   = (region < 2) ? (mt + r) : (dir * 1024 + q0 + r);
            const char* src  = srcs[region] + (size_t)grow * 512 + koff + q4 * 16;
            const uint32_t dst = sb + region * 16384 + r * 128
                               + (((uint32_t)q4 * 16) ^ (((uint32_t)(r & 7)) * 16));
            CP_ASYNC16(dst, src);
        }
    };

    const int grp = lane >> 3, lr = lane & 7;
    const uint32_t xr16 = (uint32_t)lr * 16;
    const uint32_t koffA = (uint32_t)(grp >> 1) * 16;
    const uint32_t koffB = (uint32_t)(grp & 1) * 16;
    uint32_t baseA[2], baseB[4];
#pragma unroll
    for (int i = 0; i < 2; i++) {
        const int rowA = wm * 32 + i * 16 + lr + (grp & 1) * 8;
        baseA[i] = (uint32_t)rowA * 128;
    }
#pragma unroll
    for (int j2 = 0; j2 < 4; j2++) {
        const int rowB = wn * 64 + j2 * 16 + lr + (grp >> 1) * 8;
        baseB[j2] = (uint32_t)rowB * 128;
    }

    float acc[2][8][4];
#pragma unroll
    for (int i = 0; i < 2; i++)
#pragma unroll
        for (int j = 0; j < 8; j++)
#pragma unroll
            for (int v = 0; v < 4; v++) acc[i][j][v] = 0.f;

    load_chunk(0, 0);
    CP_ASYNC_COMMIT();

#pragma unroll
    for (int c = 0; c < 4; c++) {
        if (c < 3) { load_chunk(c + 1, (c + 1) & 1); CP_ASYNC_COMMIT(); }
        if (c < 3) CP_ASYNC_WAIT(1); else CP_ASYNC_WAIT(0);
        __syncthreads();

        const uint32_t sb = st_u32 + (uint32_t)(c & 1) * GEMM_STAGE_BYTES;
        const uint32_t Ah = sb, Al = sb + 16384, Bh = sb + 32768, Bl = sb + 49152;

#pragma unroll
        for (int ks = 0; ks < 4; ks++) {
            const uint32_t offA = (((uint32_t)ks * 32) + koffA) ^ xr16;
            const uint32_t offB = (((uint32_t)ks * 32) + koffB) ^ xr16;
            uint32_t ah[2][4], al[2][4], bh[4][4], bl[4][4];
#pragma unroll
            for (int i = 0; i < 2; i++) {
                ldm4(ah[i], Ah + baseA[i] + offA);
                ldm4(al[i], Al + baseA[i] + offA);
            }
#pragma unroll
            for (int j2 = 0; j2 < 4; j2++) {
                ldm4(bh[j2], Bh + baseB[j2] + offB);
                ldm4(bl[j2], Bl + baseB[j2] + offB);
            }
#pragma unroll
            for (int i = 0; i < 2; i++)
#pragma unroll
                for (int j = 0; j < 8; j++) {
                    const int j2 = j >> 1, sel = (j & 1) * 2;
                    mma16816(acc[i][j], ah[i], bh[j2][sel], bh[j2][sel + 1]);
                    mma16816(acc[i][j], ah[i], bl[j2][sel], bl[j2][sel + 1]);
                    mma16816(acc[i][j], al[i], bh[j2][sel], bh[j2][sel + 1]);
                }
        }
        __syncthreads();
    }

    const int mrow0 = mt + wm * 32 + (lane >> 2);
    const int qcol0 = q0 + wn * 64 + (lane & 3) * 2;
#pragma unroll
    for (int i = 0; i < 2; i++) {
#pragma unroll
        for (int j = 0; j < 8; j++) {
            const int q  = qcol0 + j * 8;
            const float bx = bias_s[q - q0], by = bias_s[q - q0 + 1];
#pragma unroll
            for (int half = 0; half < 2; half++) {
                const int m  = mrow0 + i * 16 + half * 8;
                const int bb = m & 63, tt = m >> 6;
                float2 v;
                v.x = acc[i][j][half * 2 + 0] + bx;
                v.y = acc[i][j][half * 2 + 1] + by;
                *reinterpret_cast<float2*>(
                    g_Z + (((size_t)dir * 512 + tt) * 64 + bb) * 1024 + q) = v;
            }
        }
    }
}

// ---------------------------------------------------------------------------
// Recurrence v8 — two interleaved 8-batch chains per cluster (latency hiding).
// 64 CTAs = 2 dirs x 4 batch-groups(16) x 8 cluster ranks (cluster of 8).
// Per chain: R9's tensor GEMM (M=16, N=128/rank, K=256 bf16 split-3), direct
// bf16 hi/lo remote broadcast into double-buffered A tiles, mbarrier pair
// (count 8; __syncthreads + tid<8 remote arrive.release; parity=(step>>1)&1).
// Chain A's broadcast/barrier latency overlaps chain B's compute and v.v.
// SMEM: Whi 64K | Wlo 64K | A[2 chain][2 buf][hi 8K|lo 8K] 64K | mask 8K | bars.
// ---------------------------------------------------------------------------
#define RP_WHI   0
#define RP_WLO   65536
#define RP_A     131072
#define RP_MASK  196608
#define RP_BAR   204800          // [chain][buf] 8B each: chain*16 + buf*8
#define RP_SMEM  204864

__device__ __forceinline__ uint32_t swz512(uint32_t row, uint32_t kb)
{
    return row * 512 + (kb & 0x180u) + ((kb & 0x70u) ^ ((row & 7u) << 4)) + (kb & 0xFu);
}

__global__ void __cluster_dims__(8, 1, 1) __launch_bounds__(256, 1)
lstm_rec_kernel(const float* __restrict__ Wr_f, const float* __restrict__ Wr_b,
                float* __restrict__ out)
{
    extern __shared__ char smr[];
    const uint32_t sbase = smem_u32(smr);
    unsigned char* m_s = reinterpret_cast<unsigned char*>(smr + RP_MASK);

    const int tid  = threadIdx.x;
    const int bx   = blockIdx.x;
    const int dir  = bx >> 5;                  // 0..1
    const int bgrp = (bx >> 3) & 3;            // 0..3  (16 batches each)
    const int rank = bx & 7;
    const int w    = tid >> 5, lane = tid & 31;
    const int b    = lane >> 2;                // batch row 0..7 (within chain)
    const int q    = lane & 3;
    const int mg   = lane >> 3, lr = lane & 7;

    const int u_l  = 4 * w + (q >> 1) + 2 * (q & 1);
    const int ug   = (rank << 5) + u_l;        // 0..255

    // --- one-time init: Wr slice -> bf16 hi/lo SMEM -----------------------
    const float* Wr = dir ? Wr_b : Wr_f;
    for (int i = tid; i < 32768; i += 256) {
        const int n = i & 127;                 // n = u_local*4 + gate
        const int k = i >> 7;
        const float v = __ldg(&Wr[k * 1024 + (n & 3) * 256 + (rank << 5) + (n >> 2)]);
        __nv_bfloat16 hi, lo;
        split_bf16(v, hi, lo);
        const uint32_t off = swz512((uint32_t)n, (uint32_t)(k * 2));
        *reinterpret_cast<__nv_bfloat16*>(smr + RP_WHI + off) = hi;
        *reinterpret_cast<__nv_bfloat16*>(smr + RP_WLO + off) = lo;
    }
    // Zero all A tiles (64 KB) — rows 8-15 stay zero forever; h0 = 0.
    for (int i = tid; i < 4096; i += 256)
        reinterpret_cast<float4*>(smr + RP_A)[i] = make_float4(0.f, 0.f, 0.f, 0.f);
    // Mask for 16 batches
    for (int i = tid; i < 16 * 512; i += 256)
        m_s[i] = g_mask[(bgrp * 16 + (i >> 9)) * 512 + (i & 511)];
    if (tid == 0) {
        MBARRIER_INIT(sbase + RP_BAR + 0, 8);
        MBARRIER_INIT(sbase + RP_BAR + 8, 8);
        MBARRIER_INIT(sbase + RP_BAR + 16, 8);
        MBARRIER_INIT(sbase + RP_BAR + 24, 8);
    }
    __syncthreads();
    CLUSTER_SYNC();                            // bars + zeroed A cluster-visible

    // Remote bar base (rank = tid for tid<8) and pre-arm both chains' buf0.
    uint32_t rbar = 0;
    if (tid < 8) {
        rbar = mapa_rank(sbase + RP_BAR, (uint32_t)tid);
        MBAR_ARRIVE_REL_CLUSTER(rbar);          // chain A buf0
        MBAR_ARRIVE_REL_CLUSTER(rbar + 16);     // chain B buf0
    }

    // Remote A-word base addresses (storing lanes q<2 own even pair base ug).
    const uint32_t awoff = swz512((uint32_t)b, (uint32_t)(2 * (ug & ~1)));
    uint32_t rA[8];
#pragma unroll
    for (int r = 0; r < 8; r++) rA[r] = mapa_rank(sbase + RP_A + awoff, (uint32_t)r);

    // GEMM fragment bases (R9 mapping)
    const uint32_t rowA  = (uint32_t)(lr + (mg & 1) * 8);
    const uint32_t koffA = (uint32_t)((mg >> 1) * 16);
    const uint32_t rowB  = (uint32_t)(w * 16 + lr + (mg >> 1) * 8);
    const uint32_t koffB = (uint32_t)((mg & 1) * 16);
    const uint32_t swA   = (uint32_t)lr << 4;
    const uint32_t baseBhi = sbase + RP_WHI + rowB * 512;
    const uint32_t baseBlo = sbase + RP_WLO + rowB * 512;

    const float4* Z4 = reinterpret_cast<const float4*>(g_Z);
    const int t0 = dir ? 511 : 0;

    // Per-chain state
    float cstA = 0.f, hprevA = 0.f, hlastA = 0.f;
    float cstB = 0.f, hprevB = 0.f, hlastB = 0.f;
    const int bgA = bgrp * 16 + b;
    const int bgB = bgA + 8;
    float4 znA = __ldg(&Z4[(((size_t)dir * 512 + t0) * 64 + bgA) * 256 + ug]);
    float4 znB = __ldg(&Z4[(((size_t)dir * 512 + t0) * 64 + bgB) * 256 + ug]);

    for (int step = 0; step < 512; step++) {
        const int t   = dir ? (511 - step) : step;
        const int cur = step & 1;
        const int nxt = cur ^ 1;
        const uint32_t par = (uint32_t)(step >> 1) & 1u;
        const int tn = dir ? (510 - step) : (step + 1);

#pragma unroll
        for (int ch = 0; ch < 2; ch++) {
            // ---- wait for this chain's A tile (buf cur) ------------------
            MBAR_WAIT_ACQ_CLUSTER(sbase + RP_BAR + ch * 16 + cur * 8, par);

            float4 zin = ch ? znB : znA;
            if (step < 511) {
                const int bgl = ch ? bgB : bgA;
                float4 z = __ldg(&Z4[(((size_t)dir * 512 + tn) * 64 + bgl) * 256 + ug]);
                if (ch) znB = z; else znA = z;
            }

            // ---- tensor GEMM: 6 independent chains, split-3 --------------
            const uint32_t abase = sbase + RP_A + (uint32_t)ch * 32768
                                 + (uint32_t)cur * 16384;
            const uint32_t baseAhi = abase + rowA * 512;
            const uint32_t baseAlo = baseAhi + 8192;
            float a0[4] = {0.f, 0.f, 0.f, 0.f};
            float b0[4] = {0.f, 0.f, 0.f, 0.f};
            float c0v[4] = {0.f, 0.f, 0.f, 0.f};
            float a1[4] = {0.f, 0.f, 0.f, 0.f};
            float b1[4] = {0.f, 0.f, 0.f, 0.f};
            float c1v[4] = {0.f, 0.f, 0.f, 0.f};
#pragma unroll
            for (int kt = 0; kt < 16; kt++) {
                const uint32_t kbA = (uint32_t)kt * 32 + koffA;
                const uint32_t kbB = (uint32_t)kt * 32 + koffB;
                const uint32_t offA = (kbA & 0x180u) + ((kbA & 0x70u) ^ swA);
                const uint32_t offB = (kbB & 0x180u) + ((kbB & 0x70u) ^ swA);
                uint32_t ah[4], al[4], bh[4], bl[4];
                ldm4(ah, baseAhi + offA);
                ldm4(al, baseAlo + offA);
                ldm4(bh, baseBhi + offB);
                ldm4(bl, baseBlo + offB);
                mma16816(a0, ah, bh[0], bh[1]);
                mma16816(b0, ah, bl[0], bl[1]);
                mma16816(c0v, al, bh[0], bh[1]);
                mma16816(a1, ah, bh[2], bh[3]);
                mma16816(b1, ah, bl[2], bl[3]);
                mma16816(c1v, al, bh[2], bh[3]);
            }
            float acc0[2], acc1[2];
            acc0[0] = a0[0] + b0[0] + c0v[0];
            acc0[1] = a0[1] + b0[1] + c0v[1];
            acc1[0] = a1[0] + b1[0] + c1v[0];
            acc1[1] = a1[1] + b1[1] + c1v[1];

            // ---- gate assembly (R9-verified lane-pair exchange) ----------
            const bool odd = (q & 1) != 0;
            const float s0 = odd ? acc0[0] : acc1[0];
            const float s1 = odd ? acc0[1] : acc1[1];
            const float r0 = __shfl_xor_sync(0xffffffffu, s0, 1);
            const float r1 = __shfl_xor_sync(0xffffffffu, s1, 1);
            float zi = odd ? r0 : acc0[0];
            float zf = odd ? r1 : acc0[1];
            float zc = odd ? acc1[0] : r0;
            float zo = odd ? acc1[1] : r1;
            zi += zin.x; zf += zin.y; zc += zin.z; zo += zin.w;

            const float gi = ftanh(zi);
            const float gf = ftanh(zf);
            const float gc = ftanh(zc);
            const float go = ftanh(zo);
            const float cstp = ch ? cstB : cstA;
            const float hpp  = ch ? hprevB : hprevA;
            const float cn = fmaf(gf, cstp, gi * gc);
            const float hn = go * ftanh(cn);

            const int  mrow = ch ? (b + 8) : b;
            const bool mk = m_s[(mrow << 9) + t] != 0;
            const float hv = mk ? hn : hpp;
            const float cv = mk ? cn : cstp;
            if (ch) { cstB = cv; hprevB = hv; hlastB = hv; }
            else    { cstA = cv; hprevA = hv; hlastA = hv; }

            const int bgl = ch ? bgB : bgA;
            out[((size_t)bgl * 512 + t) * 512 + (dir << 8) + ug] = hv;

            // ---- broadcast h (bf16 hi/lo packed u32) to all 8 A[nxt] -----
            const float hvp = __shfl_xor_sync(0xffffffffu, hv, 2);  // partner u
            if (q < 2) {
                __nv_bfloat16 he, le, ho, lo2;
                split_bf16(hv,  he, le);
                split_bf16(hvp, ho, lo2);
                const uint32_t wh = (uint32_t)*reinterpret_cast<unsigned short*>(&he)
                                  | ((uint32_t)*reinterpret_cast<unsigned short*>(&ho) << 16);
                const uint32_t wl = (uint32_t)*reinterpret_cast<unsigned short*>(&le)
                                  | ((uint32_t)*reinterpret_cast<unsigned short*>(&lo2) << 16);
                const uint32_t bo = (uint32_t)ch * 32768 + (uint32_t)nxt * 16384;
#pragma unroll
                for (int r = 0; r < 8; r++) {
                    ST_CLUSTER_U32(rA[r] + bo, wh);
                    ST_CLUSTER_U32(rA[r] + bo + 8192, wl);
                }
            }
            __syncthreads();                 // cumulativity: all stores done
            if (tid < 8)
                MBAR_ARRIVE_REL_CLUSTER(rbar + ch * 16 + nxt * 8);
        }
    }

    out[16777216 + (size_t)bgA * 512 + (dir << 8) + ug] = hlastA;
    out[16777216 + (size_t)bgB * 512 + (dir << 8) + ug] = hlastB;

    CLUSTER_SYNC();   // no CTA exits while remote stores may target its SMEM
}

// ---------------------------------------------------------------------------
// Launch
// ---------------------------------------------------------------------------
extern "C" void kernel_launch(void* const* d_in, const int* in_sizes, int n_in,
                              void* d_out, int out_size)
{
    const float* x    = (const float*)d_in[0];
    const float* Wk_f = (const float*)d_in[1];
    const float* Wr_f = (const float*)d_in[2];
    const float* b_f  = (const float*)d_in[3];
    const float* Wk_b = (const float*)d_in[4];
    const float* Wr_b = (const float*)d_in[5];
    const float* b_b  = (const float*)d_in[6];
    float* out = (float*)d_out;

    mask_kernel<<<4096, 256>>>(x);
    convert_x_kernel<<<8192, 256>>>(x);
    convert_w_kernel<<<2048, 256>>>(Wk_f, Wk_b);

    cudaFuncSetAttribute(gemm_mma_kernel,
                         cudaFuncAttributeMaxDynamicSharedMemorySize, GEMM_SMEM_BYTES);
    dim3 gg(256, 16);
    gemm_mma_kernel<<<gg, 256, GEMM_SMEM_BYTES>>>(b_f, b_b);

    cudaFuncSetAttribute(lstm_rec_kernel,
                         cudaFuncAttributeMaxDynamicSharedMemorySize, RP_SMEM);
    lstm_rec_kernel<<<64, 256, RP_SMEM>>>(Wr_f, Wr_b, out);
}